// round 2
// baseline (speedup 1.0000x reference)
#include <cuda_runtime.h>
#include <math.h>
#include <stdint.h>

#define CDIM 512
#define KDIM 1024
#define NB   16
#define LMAX 4096

#define TM 64
#define TN 128
#define TK 16
#define XN (TN + 4)

// Scratch (static device globals; no allocations anywhere)
__device__ float g_wrt[(size_t)KDIM * 3 * CDIM];           // reordered W: [k][o], 6 MB
__device__ float g_m[(size_t)NB * LMAX * CDIM];            // merged sequence, 128 MB
__device__ float g_buf0[(size_t)NB * 2048 * CDIM];         // ping
__device__ float g_buf1[(size_t)NB * 2048 * CDIM];         // pong

// ---------------------------------------------------------------------------
// Reorder W[o][k2][j] -> Wrt[k][o] with effective k = j*512 + k2 flattening:
// Weff[o][k] = W[o*1024 + 2*(k&511) + (k>>9)]
// ---------------------------------------------------------------------------
__global__ void prep_w_kernel(const float* __restrict__ W) {
    int idx = blockIdx.x * blockDim.x + threadIdx.x;
    if (idx >= KDIM * 3 * CDIM) return;
    int k = idx / 1536;
    int o = idx - k * 1536;
    g_wrt[idx] = W[(size_t)o * 1024 + 2 * (k & 511) + (k >> 9)];
}

// ---------------------------------------------------------------------------
// Merge copy: m[b][i][c] = h[b][c][i+half] for i in [half, Nfp2)  (transpose)
// Handles Nfp2==1 terminal case by also writing d_out.
// ---------------------------------------------------------------------------
__global__ void merge_copy_kernel(const float* __restrict__ h,
                                  const int* __restrict__ Nptr,
                                  float* __restrict__ dout) {
    __shared__ float tile[32][33];
    int b = blockIdx.z;
    int n = Nptr[b];
    if (n <= 0) return;
    int nfp2 = 1 << (31 - __clz(n));
    int half = n - nfp2;
    int i0 = blockIdx.x * 32, c0 = blockIdx.y * 32;
    if (i0 >= nfp2) return;
    if (i0 + 32 <= half) return;
    int tx = threadIdx.x, ty = threadIdx.y;
#pragma unroll
    for (int r = 0; r < 4; r++) {
        int c = c0 + ty + r * 8;
        int i = i0 + tx;
        if (i >= half && i < nfp2)
            tile[ty + r * 8][tx] = h[((size_t)b * CDIM + c) * LMAX + i + half];
    }
    __syncthreads();
#pragma unroll
    for (int r = 0; r < 4; r++) {
        int i = i0 + ty + r * 8;
        int c = c0 + tx;
        if (i >= half && i < nfp2) {
            float v = tile[tx][ty + r * 8];
            g_m[((size_t)b * LMAX + i) * CDIM + c] = v;
            if (nfp2 == 1 && i == 0) dout[b * CDIM + c] = v;
        }
    }
}

// ---------------------------------------------------------------------------
// Big tiled GEMM + gated epilogue.
// MODE 0: merge phase. X[k][p]: k<512 -> h[b][k][2p], k>=512 -> h[b][k-512][2p+1]
//         P = N - Nfp2 (the "half" prefix), output -> g_m[b][p][:]
// MODE 1: tree level. X column p = src[b][2p..2p+1][:] (contiguous 1024 floats)
//         P = Nfp2 >> level, output -> dst buffer; if P==1 also d_out.
// CTA tile: 64 channels x 128 pairs x 3 gates.  256 threads, thread tile 4x8x3.
// ---------------------------------------------------------------------------
template <int MODE>
__global__ void __launch_bounds__(256, 1)
gemm_big_kernel(const float* __restrict__ src, float* __restrict__ dst,
                float* __restrict__ dout, const float* __restrict__ bias,
                const int* __restrict__ Nptr, int level, int in_elems,
                int out_elems) {
    int b = blockIdx.z;
    int n = Nptr[b];
    if (n <= 0) return;
    int nfp2 = 1 << (31 - __clz(n));
    int P = (MODE == 0) ? (n - nfp2) : (nfp2 >> level);
    if (P <= 0) return;
    int p0 = blockIdx.y * TN;
    if (p0 >= P) return;
    int cb = blockIdx.x * TM;

    int tid = threadIdx.x;
    int tcy = tid >> 4;            // channel sub-tile (0..15)
    int tcx = tid & 15;            // pair sub-tile   (0..15)
    int lkk = tid >> 4;            // W load: kk index
    int lc4 = (tid & 15) << 2;     // W load: channel*4
    int lp  = tid >> 1;            // X load: pair index (0..127)
    int lk8 = (tid & 1) << 3;      // X load: k offset (0 or 8)

    __shared__ float Ws[2][3][TK][TM];
    __shared__ float Xs[2][TK][XN];

    float acc[3][4][8];
#pragma unroll
    for (int g = 0; g < 3; g++)
#pragma unroll
        for (int i = 0; i < 4; i++)
#pragma unroll
            for (int j = 0; j < 8; j++) acc[g][i][j] = 0.f;

    int pg = p0 + lp;
    bool pv = pg < P;
    int pgc = pv ? pg : 0;
    const float* xcol = (MODE == 1)
        ? src + ((size_t)b * in_elems + 2 * (size_t)pgc) * CDIM
        : src;

    float wreg[3][4];
    float xreg[8];

    auto loadW = [&](int kc) {
        size_t kb = (size_t)(kc * TK + lkk) * 1536 + cb + lc4;
#pragma unroll
        for (int g = 0; g < 3; g++) {
            float4 t = *(const float4*)&g_wrt[kb + (size_t)g * 512];
            wreg[g][0] = t.x; wreg[g][1] = t.y; wreg[g][2] = t.z; wreg[g][3] = t.w;
        }
    };
    auto loadX = [&](int kc) {
        int k0 = kc * TK + lk8;
        if (MODE == 1) {
            if (pv) {
                float4 t0 = *(const float4*)&xcol[k0];
                float4 t1 = *(const float4*)&xcol[k0 + 4];
                xreg[0] = t0.x; xreg[1] = t0.y; xreg[2] = t0.z; xreg[3] = t0.w;
                xreg[4] = t1.x; xreg[5] = t1.y; xreg[6] = t1.z; xreg[7] = t1.w;
            } else {
#pragma unroll
                for (int j = 0; j < 8; j++) xreg[j] = 0.f;
            }
        } else {
#pragma unroll
            for (int j = 0; j < 8; j++) {
                int k = k0 + j;
                xreg[j] = pv ? src[((size_t)b * CDIM + (k & 511)) * LMAX +
                                   2 * pgc + (k >> 9)]
                             : 0.f;
            }
        }
    };
    auto stsW = [&](int bf) {
#pragma unroll
        for (int g = 0; g < 3; g++)
            *(float4*)&Ws[bf][g][lkk][lc4] =
                make_float4(wreg[g][0], wreg[g][1], wreg[g][2], wreg[g][3]);
    };
    auto stsX = [&](int bf) {
#pragma unroll
        for (int j = 0; j < 8; j++) Xs[bf][lk8 + j][lp] = xreg[j];
    };
    auto compute = [&](int bf) {
#pragma unroll
        for (int kk = 0; kk < TK; kk++) {
            float av[3][4], xv[8];
#pragma unroll
            for (int g = 0; g < 3; g++) {
                float4 t = *(const float4*)&Ws[bf][g][kk][tcy << 2];
                av[g][0] = t.x; av[g][1] = t.y; av[g][2] = t.z; av[g][3] = t.w;
            }
            float4 u0 = *(const float4*)&Xs[bf][kk][tcx << 2];
            float4 u1 = *(const float4*)&Xs[bf][kk][64 + (tcx << 2)];
            xv[0] = u0.x; xv[1] = u0.y; xv[2] = u0.z; xv[3] = u0.w;
            xv[4] = u1.x; xv[5] = u1.y; xv[6] = u1.z; xv[7] = u1.w;
#pragma unroll
            for (int g = 0; g < 3; g++)
#pragma unroll
                for (int i = 0; i < 4; i++)
#pragma unroll
                    for (int j = 0; j < 8; j++)
                        acc[g][i][j] = fmaf(av[g][i], xv[j], acc[g][i][j]);
        }
    };

    loadW(0);
    loadX(0);
    stsW(0);
    stsX(0);
    __syncthreads();
#pragma unroll 1
    for (int kc = 0; kc < KDIM / TK; kc++) {
        int bf = kc & 1;
        if (kc + 1 < KDIM / TK) { loadW(kc + 1); loadX(kc + 1); }
        compute(bf);
        if (kc + 1 < KDIM / TK) {
            stsW(bf ^ 1);
            stsX(bf ^ 1);
            __syncthreads();
        }
    }

    // gated epilogue: out = sig(g)*(l - tanh(r)) + tanh(r)
    int cth = cb + (tcy << 2);
    float bl[4], br[4], bg[4];
#pragma unroll
    for (int i = 0; i < 4; i++) {
        bl[i] = bias[cth + i];
        br[i] = bias[512 + cth + i];
        bg[i] = bias[1024 + cth + i];
    }
#pragma unroll
    for (int jj = 0; jj < 2; jj++) {
#pragma unroll
        for (int j = 0; j < 4; j++) {
            int p = p0 + jj * 64 + (tcx << 2) + j;
            if (p < P) {
                int jx = jj * 4 + j;
                float ov[4];
#pragma unroll
                for (int i = 0; i < 4; i++) {
                    float l  = acc[0][i][jx] + bl[i];
                    float r  = tanhf(acc[1][i][jx] + br[i]);
                    float gg = 1.f / (1.f + expf(-(acc[2][i][jx] + bg[i])));
                    ov[i] = gg * (l - r) + r;
                }
                float4 o4 = make_float4(ov[0], ov[1], ov[2], ov[3]);
                *(float4*)&dst[((size_t)b * out_elems + p) * CDIM + cth] = o4;
                if (MODE == 1 && P == 1)
                    *(float4*)&dout[b * CDIM + cth] = o4;
            }
        }
    }
}

// ---------------------------------------------------------------------------
// Small kernel for tail levels (pairs <= 64). CTA: 192 outputs x up to 8 pairs.
// X tile resident in smem (32 KB); W streamed from L2 (broadcast across 16
// batches' CTAs, so it stays hot).
// ---------------------------------------------------------------------------
__global__ void __launch_bounds__(192, 2)
gemm_small_kernel(const float* __restrict__ src, float* __restrict__ dst,
                  float* __restrict__ dout, const float* __restrict__ bias,
                  const int* __restrict__ Nptr, int level, int in_elems,
                  int out_elems) {
    int b = blockIdx.z;
    int n = Nptr[b];
    if (n <= 0) return;
    int nfp2 = 1 << (31 - __clz(n));
    int P = nfp2 >> level;
    if (P <= 0) return;
    int p0 = blockIdx.y * 8;
    if (p0 >= P) return;
    int cb = blockIdx.x * 64;
    int tid = threadIdx.x;

    __shared__ float Xs[KDIM][8];
    __shared__ float Sg[3][64][8];

    for (int idx = tid; idx < KDIM * 8; idx += 192) {
        int p = idx >> 10, k = idx & 1023;
        float v = 0.f;
        if (p0 + p < P)
            v = src[((size_t)b * in_elems + 2 * (size_t)(p0 + p)) * CDIM + k];
        Xs[k][p] = v;
    }
    __syncthreads();

    int g = tid / 64, cl = tid - g * 64;
    int o = g * 512 + cb + cl;
    float acc[8];
#pragma unroll
    for (int p = 0; p < 8; p++) acc[p] = 0.f;

#pragma unroll 4
    for (int k = 0; k < KDIM; k++) {
        float w = g_wrt[(size_t)k * 1536 + o];
        float4 xa = *(const float4*)&Xs[k][0];
        float4 xb = *(const float4*)&Xs[k][4];
        acc[0] = fmaf(w, xa.x, acc[0]);
        acc[1] = fmaf(w, xa.y, acc[1]);
        acc[2] = fmaf(w, xa.z, acc[2]);
        acc[3] = fmaf(w, xa.w, acc[3]);
        acc[4] = fmaf(w, xb.x, acc[4]);
        acc[5] = fmaf(w, xb.y, acc[5]);
        acc[6] = fmaf(w, xb.z, acc[6]);
        acc[7] = fmaf(w, xb.w, acc[7]);
    }
    float bb = bias[o];
#pragma unroll
    for (int p = 0; p < 8; p++) Sg[g][cl][p] = acc[p] + bb;
    __syncthreads();

    for (int idx = tid; idx < 64 * 8; idx += 192) {
        int c = idx & 63, p = idx >> 6;
        if (p0 + p < P) {
            float l  = Sg[0][c][p];
            float r  = tanhf(Sg[1][c][p]);
            float gg = 1.f / (1.f + expf(-Sg[2][c][p]));
            float v = gg * (l - r) + r;
            dst[((size_t)b * out_elems + p0 + p) * CDIM + cb + c] = v;
            if (P == 1) dout[b * CDIM + cb + c] = v;
        }
    }
}

// ---------------------------------------------------------------------------
// Host: 15 launches, all graph-capturable (no sync, no alloc, no memcpy).
// ---------------------------------------------------------------------------
extern "C" void kernel_launch(void* const* d_in, const int* in_sizes, int n_in,
                              void* d_out, int out_size) {
    const float* h    = (const float*)d_in[0];
    const float* W    = (const float*)d_in[1];
    const float* bias = (const float*)d_in[2];
    const int*   N    = (const int*)d_in[3];
    float* dout = (float*)d_out;

    float *pm, *pb0, *pb1;
    cudaGetSymbolAddress((void**)&pm, g_m);
    cudaGetSymbolAddress((void**)&pb0, g_buf0);
    cudaGetSymbolAddress((void**)&pb1, g_buf1);

    // 1. reorder W
    prep_w_kernel<<<(KDIM * 3 * CDIM + 255) / 256, 256>>>(W);

    // 2. merge copy (suffix part + Nfp2==1 terminal)
    merge_copy_kernel<<<dim3(LMAX / 32, CDIM / 32, NB), dim3(32, 8)>>>(h, N, dout);

    // 3. merge gemm (prefix part: pairs from h)
    gemm_big_kernel<0><<<dim3(8, 16, NB), 256>>>(h, pm, dout, bias, N, 0, 0, LMAX);

    // 4. tree levels
    const float* srcp = pm;
    int in_e = LMAX;
    float* bufs[2] = {pb0, pb1};
    for (int lvl = 1; lvl <= 12; lvl++) {
        int pmax = LMAX >> lvl;
        float* d = bufs[lvl & 1];
        if (pmax >= TN) {
            gemm_big_kernel<1><<<dim3(8, (pmax + TN - 1) / TN, NB), 256>>>(
                srcp, d, dout, bias, N, lvl, in_e, 2048);
        } else {
            gemm_small_kernel<<<dim3(8, (pmax + 7) / 8, NB), 192>>>(
                srcp, d, dout, bias, N, lvl, in_e, 2048);
        }
        srcp = d;
        in_e = 2048;
    }
}

// round 4
// speedup vs baseline: 1.7899x; 1.7899x over previous
#include <cuda_runtime.h>
#include <cuda_bf16.h>
#include <math.h>
#include <stdint.h>

#define CDIM 512
#define KDIM 1024
#define NB   16
#define LMAX 4096

// ---------------------------------------------------------------------------
// sm_80-compatible PTX helpers (NO tcgen05 — harness targets base sm_100)
// ---------------------------------------------------------------------------
__device__ __forceinline__ uint32_t smem_u32(const void* p) {
    uint32_t a;
    asm("{ .reg .u64 t; cvta.to.shared.u64 t, %1; cvt.u32.u64 %0, t; }"
        : "=r"(a) : "l"(p));
    return a;
}
__device__ __forceinline__ void cpa16(uint32_t d, const void* s) {
    asm volatile("cp.async.cg.shared.global [%0], [%1], 16;" :: "r"(d), "l"(s));
}
#define CP_COMMIT() asm volatile("cp.async.commit_group;" ::: "memory")
#define CP_WAIT1()  asm volatile("cp.async.wait_group 1;" ::: "memory")

__device__ __forceinline__ uint32_t lds32(uint32_t a) {
    uint32_t v;
    asm volatile("ld.shared.b32 %0, [%1];" : "=r"(v) : "r"(a));
    return v;
}
__device__ __forceinline__ void ldsm4(uint32_t* r, uint32_t a) {
    asm volatile("ldmatrix.sync.aligned.m8n8.x4.shared.b16 {%0,%1,%2,%3}, [%4];"
                 : "=r"(r[0]), "=r"(r[1]), "=r"(r[2]), "=r"(r[3]) : "r"(a));
}
__device__ __forceinline__ void mma_bf16(float* d, const uint32_t* a, const uint32_t* b) {
    asm volatile("mma.sync.aligned.m16n8k16.row.col.f32.bf16.bf16.f32 "
                 "{%0,%1,%2,%3}, {%4,%5,%6,%7}, {%8,%9}, {%0,%1,%2,%3};"
                 : "+f"(d[0]), "+f"(d[1]), "+f"(d[2]), "+f"(d[3])
                 : "r"(a[0]), "r"(a[1]), "r"(a[2]), "r"(a[3]), "r"(b[0]), "r"(b[1]));
}

// ---------------------------------------------------------------------------
// Scratch (static device globals; no allocations anywhere)
// ---------------------------------------------------------------------------
__device__ float          g_wrt[(size_t)KDIM * 3 * CDIM];      // fp32 [k][o] (SIMT tail)
__device__ __nv_bfloat16  g_whi[(size_t)3 * CDIM * KDIM];      // bf16 [o][k]
__device__ __nv_bfloat16  g_wlo[(size_t)3 * CDIM * KDIM];
__device__ __nv_bfloat16  g_s0hi[(size_t)NB * LMAX * CDIM];    // [b][i][c]
__device__ __nv_bfloat16  g_s0lo[(size_t)NB * LMAX * CDIM];
__device__ __nv_bfloat16  g_curhi[(size_t)NB * LMAX * CDIM];
__device__ __nv_bfloat16  g_curlo[(size_t)NB * LMAX * CDIM];
__device__ __nv_bfloat16  g_p0hi[(size_t)NB * 2048 * CDIM];
__device__ __nv_bfloat16  g_p0lo[(size_t)NB * 2048 * CDIM];
__device__ __nv_bfloat16  g_p1hi[(size_t)NB * 2048 * CDIM];
__device__ __nv_bfloat16  g_p1lo[(size_t)NB * 2048 * CDIM];

// ---------------------------------------------------------------------------
// prep: W fp32 -> (g_wrt fp32 [k][o]) + (g_whi/g_wlo bf16 [o][k])
// k' = j*512 + c;  Weff[o][k'] = W[o*1024 + 2*(k'&511) + (k'>>9)]
// ---------------------------------------------------------------------------
__global__ void prep_w_kernel(const float* __restrict__ W) {
    int idx = blockIdx.x * blockDim.x + threadIdx.x;   // idx = o*1024 + k
    if (idx >= 3 * CDIM * KDIM) return;
    int o = idx >> 10, k = idx & 1023;
    float w = W[(size_t)o * 1024 + 2 * (k & 511) + (k >> 9)];
    g_wrt[(size_t)k * 1536 + o] = w;
    __nv_bfloat16 hi = __float2bfloat16(w);
    g_whi[idx] = hi;
    g_wlo[idx] = __float2bfloat16(w - __bfloat162float(hi));
}

// ---------------------------------------------------------------------------
// pack: transpose h[b][c][i] -> s0 [b][i][c] (bf16 hi/lo), i < n.
// Also: suffix copy cur[i-half] = s0[i] for i in [2*half, n) when half > 0.
// Also: nfp2 == 1 terminal -> d_out.
// ---------------------------------------------------------------------------
__global__ void pack_kernel(const float* __restrict__ h, const int* __restrict__ Nptr,
                            float* __restrict__ dout) {
    __shared__ float tile[32][33];
    int b = blockIdx.z;
    int n = Nptr[b];
    if (n <= 0) return;
    int nfp2 = 1 << (31 - __clz(n));
    int half = n - nfp2;
    int i0 = blockIdx.x * 32, c0 = blockIdx.y * 32;
    if (i0 >= n) return;
    int tx = threadIdx.x, ty = threadIdx.y;
#pragma unroll
    for (int r = 0; r < 4; r++) {
        int c = c0 + ty + r * 8, i = i0 + tx;
        if (i < n) tile[ty + r * 8][tx] = h[((size_t)b * CDIM + c) * LMAX + i];
    }
    __syncthreads();
#pragma unroll
    for (int r = 0; r < 4; r++) {
        int i = i0 + ty + r * 8, c = c0 + tx;
        if (i < n) {
            float v = tile[tx][ty + r * 8];
            __nv_bfloat16 hi = __float2bfloat16(v);
            __nv_bfloat16 lo = __float2bfloat16(v - __bfloat162float(hi));
            size_t o = ((size_t)b * LMAX + i) * CDIM + c;
            g_s0hi[o] = hi;
            g_s0lo[o] = lo;
            if (half > 0 && i >= 2 * half) {
                size_t oc = ((size_t)b * LMAX + (i - half)) * CDIM + c;
                g_curhi[oc] = hi;
                g_curlo[oc] = lo;
            }
            if (nfp2 == 1 && i == 0) dout[b * CDIM + c] = v;
        }
    }
}

// ---------------------------------------------------------------------------
// HMMA level kernel (legacy mma.sync, bf16 3-term split).
// CTA: 128 channels x 3 gates (M=384) x 64 pairs.  256 threads, 8 warps
// (4 ch-groups x 2 pair-groups).  Warp: 32ch x 32p x 3g -> 96 fp32 accums.
// K=1024, BK=32, cp.async 2-stage pipeline.
// SMEM stage: A(hi,lo) 2x384x80B + B(hi,lo) 2x64x80B = 71680B; x2 = 143360B.
// ---------------------------------------------------------------------------
#define STAGE   71680
#define SM_TOT  (2 * STAGE)
#define A_LO    30720
#define B_OFF   61440
#define B_LO    5120

__global__ void __launch_bounds__(256, 1)
mma_level_kernel(const __nv_bfloat16* __restrict__ shi, const __nv_bfloat16* __restrict__ slo,
                 const __nv_bfloat16* __restrict__ ahi, const __nv_bfloat16* __restrict__ alo,
                 __nv_bfloat16* __restrict__ dhi, __nv_bfloat16* __restrict__ dlo,
                 float* __restrict__ dout, const float* __restrict__ bias,
                 const int* __restrict__ Nptr, int level, int srcRows, int dstRows) {
    int b = blockIdx.z;
    int n = Nptr[b];
    if (n <= 0) return;
    int nfp2 = 1 << (31 - __clz(n));
    int half = n - nfp2;
    int P = (level == 0) ? half : (nfp2 >> level);
    if (P <= 0) return;
    int p0 = blockIdx.y * 64;
    if (p0 >= P) return;
    int cb = blockIdx.x * 128;

    const __nv_bfloat16* xhi = shi;
    const __nv_bfloat16* xlo = slo;
    if (level == 1 && half == 0) { xhi = ahi; xlo = alo; }   // pow2 n: read s0

    extern __shared__ char sm[];
    uint32_t sb = smem_u32(sm);
    int tid = threadIdx.x, lane = tid & 31, wid = tid >> 5;
    int wc = wid >> 1, wp = wid & 1;

    float acc[3][2][4][4];
#pragma unroll
    for (int g = 0; g < 3; g++)
#pragma unroll
        for (int mf = 0; mf < 2; mf++)
#pragma unroll
            for (int nf = 0; nf < 4; nf++)
#pragma unroll
                for (int e = 0; e < 4; e++) acc[g][mf][nf][e] = 0.f;

    const char* whiB = (const char*)g_whi;
    const char* wloB = (const char*)g_wlo;

    auto issue = [&](int kc, int buf) {
        uint32_t sbase = sb + buf * STAGE;
        // A: 3072 16B chunks / 256 threads = 12 per thread
#pragma unroll
        for (int j = 0; j < 12; j++) {
            int id = tid + 256 * j;
            int hl = id >= 1536;
            int rem = id - hl * 1536;
            int row = rem >> 2, c = rem & 3;
            int grow = ((row >> 7) << 9) + cb + (row & 127);   // gate*512 + cb + local
            const char* g = (hl ? wloB : whiB) +
                            (size_t)grow * 2048 + kc * 64 + c * 16;
            cpa16(sbase + hl * A_LO + row * 80 + c * 16, g);
        }
        // B: 512 chunks / 256 threads = 2 per thread
#pragma unroll
        for (int j = 0; j < 2; j++) {
            int id = tid + 256 * j;
            int hl = id >> 8;
            int rem = id & 255;
            int nr = rem >> 2, c = rem & 3;
            int p = p0 + nr;
            if (p >= P) p = P - 1;
            const char* g = (const char*)(hl ? xlo : xhi) +
                            ((size_t)b * srcRows + 2 * (size_t)p) * 1024 +
                            ((kc >> 4) << 10) + ((kc & 15) << 6) + c * 16;
            cpa16(sbase + B_OFF + hl * B_LO + nr * 80 + c * 16, g);
        }
    };

    auto compute_half = [&](int buf, int h) {
        uint32_t sbA = sb + buf * STAGE;
        uint32_t sbB = sbA + B_OFF;
        uint32_t bh[4][2], bl[4][2];
#pragma unroll
        for (int nf = 0; nf < 4; nf++) {
            int nn = wp * 32 + nf * 8 + (lane >> 2);
            uint32_t off = nn * 80 + h * 32 + (lane & 3) * 4;
            bh[nf][0] = lds32(sbB + off);
            bh[nf][1] = lds32(sbB + off + 16);
            bl[nf][0] = lds32(sbB + B_LO + off);
            bl[nf][1] = lds32(sbB + B_LO + off + 16);
        }
#pragma unroll
        for (int g = 0; g < 3; g++) {
#pragma unroll
            for (int mf = 0; mf < 2; mf++) {
                int row = g * 128 + wc * 32 + mf * 16 + (lane & 15);
                uint32_t byte = ((lane >> 4) << 4) + h * 32;
                uint32_t ah[4], al[4];
                ldsm4(ah, sbA + row * 80 + byte);
                ldsm4(al, sbA + A_LO + row * 80 + byte);
#pragma unroll
                for (int nf = 0; nf < 4; nf++) {
                    mma_bf16(acc[g][mf][nf], ah, bh[nf]);
                    mma_bf16(acc[g][mf][nf], ah, bl[nf]);
                    mma_bf16(acc[g][mf][nf], al, bh[nf]);
                }
            }
        }
    };

    issue(0, 0); CP_COMMIT();
    issue(1, 1); CP_COMMIT();
#pragma unroll 1
    for (int kc = 0; kc < 32; kc++) {
        CP_WAIT1();
        __syncthreads();
        int buf = kc & 1;
        compute_half(buf, 0);
        compute_half(buf, 1);
        __syncthreads();
        if (kc + 2 < 32) issue(kc + 2, buf);
        CP_COMMIT();
    }

    // fused gated epilogue
    int rbase = lane >> 2, cpair = (lane & 3) << 1;
    bool wout = (level > 0 && P == 1);
#pragma unroll
    for (int mf = 0; mf < 2; mf++) {
#pragma unroll
        for (int e2 = 0; e2 < 2; e2++) {
            int ch = cb + wc * 32 + mf * 16 + rbase + e2 * 8;
            float bL = bias[ch], bR = bias[512 + ch], bG = bias[1024 + ch];
#pragma unroll
            for (int nf = 0; nf < 4; nf++) {
#pragma unroll
                for (int e1 = 0; e1 < 2; e1++) {
                    int p = p0 + wp * 32 + nf * 8 + cpair + e1;
                    if (p < P) {
                        int e = e2 * 2 + e1;
                        float l  = acc[0][mf][nf][e] + bL;
                        float r  = tanhf(acc[1][mf][nf][e] + bR);
                        float gg = 1.f / (1.f + __expf(-(acc[2][mf][nf][e] + bG)));
                        float v  = gg * (l - r) + r;
                        __nv_bfloat16 hi = __float2bfloat16(v);
                        __nv_bfloat16 lo = __float2bfloat16(v - __bfloat162float(hi));
                        size_t o = ((size_t)b * dstRows + p) * CDIM + ch;
                        dhi[o] = hi;
                        dlo[o] = lo;
                        if (wout && p == 0) dout[b * CDIM + ch] = v;
                    }
                }
            }
        }
    }
}

// ---------------------------------------------------------------------------
// SIMT tail kernel (pairs <= 64), bf16 hi/lo in/out, fp32 W from g_wrt
// ---------------------------------------------------------------------------
__global__ void __launch_bounds__(192, 2)
gemm_small_kernel(const __nv_bfloat16* __restrict__ shi, const __nv_bfloat16* __restrict__ slo,
                  __nv_bfloat16* __restrict__ dhi, __nv_bfloat16* __restrict__ dlo,
                  float* __restrict__ dout, const float* __restrict__ bias,
                  const int* __restrict__ Nptr, int level, int srcRows, int dstRows) {
    int b = blockIdx.z;
    int n = Nptr[b];
    if (n <= 0) return;
    int nfp2 = 1 << (31 - __clz(n));
    int P = nfp2 >> level;
    if (P <= 0) return;
    int p0 = blockIdx.y * 8;
    if (p0 >= P) return;
    int cb = blockIdx.x * 64;
    int tid = threadIdx.x;

    __shared__ float Xs[KDIM][8];
    __shared__ float Sg[3][64][8];

    for (int idx = tid; idx < KDIM * 8; idx += 192) {
        int p = idx >> 10, k = idx & 1023;
        float v = 0.f;
        if (p0 + p < P) {
            size_t o = ((size_t)b * srcRows + 2 * (size_t)(p0 + p)) * 512 + k;
            v = __bfloat162float(shi[o]) + __bfloat162float(slo[o]);
        }
        Xs[k][p] = v;
    }
    __syncthreads();

    int g = tid / 64, cl = tid - g * 64;
    int o = g * 512 + cb + cl;
    float acc[8];
#pragma unroll
    for (int p = 0; p < 8; p++) acc[p] = 0.f;
#pragma unroll 4
    for (int k = 0; k < KDIM; k++) {
        float w = g_wrt[(size_t)k * 1536 + o];
        float4 xa = *(const float4*)&Xs[k][0];
        float4 xb = *(const float4*)&Xs[k][4];
        acc[0] = fmaf(w, xa.x, acc[0]); acc[1] = fmaf(w, xa.y, acc[1]);
        acc[2] = fmaf(w, xa.z, acc[2]); acc[3] = fmaf(w, xa.w, acc[3]);
        acc[4] = fmaf(w, xb.x, acc[4]); acc[5] = fmaf(w, xb.y, acc[5]);
        acc[6] = fmaf(w, xb.z, acc[6]); acc[7] = fmaf(w, xb.w, acc[7]);
    }
    float bb = bias[o];
#pragma unroll
    for (int p = 0; p < 8; p++) Sg[g][cl][p] = acc[p] + bb;
    __syncthreads();

    for (int idx = tid; idx < 64 * 8; idx += 192) {
        int c = idx & 63, p = idx >> 6;
        if (p0 + p < P) {
            float l  = Sg[0][c][p];
            float rr = tanhf(Sg[1][c][p]);
            float gg = 1.f / (1.f + __expf(-Sg[2][c][p]));
            float v  = gg * (l - rr) + rr;
            __nv_bfloat16 hi = __float2bfloat16(v);
            __nv_bfloat16 lo = __float2bfloat16(v - __bfloat162float(hi));
            size_t oo = ((size_t)b * dstRows + p0 + p) * CDIM + cb + c;
            dhi[oo] = hi;
            dlo[oo] = lo;
            if (P == 1) dout[b * CDIM + cb + c] = v;
        }
    }
}

// ---------------------------------------------------------------------------
// Host
// ---------------------------------------------------------------------------
extern "C" void kernel_launch(void* const* d_in, const int* in_sizes, int n_in,
                              void* d_out, int out_size) {
    const float* h    = (const float*)d_in[0];
    const float* W    = (const float*)d_in[1];
    const float* bias = (const float*)d_in[2];
    const int*   N    = (const int*)d_in[3];
    float* dout = (float*)d_out;

    cudaFuncSetAttribute(mma_level_kernel,
                         cudaFuncAttributeMaxDynamicSharedMemorySize, SM_TOT);

    __nv_bfloat16 *s0h, *s0l, *cuh, *cul, *p0h, *p0l, *p1h, *p1l;
    cudaGetSymbolAddress((void**)&s0h, g_s0hi);
    cudaGetSymbolAddress((void**)&s0l, g_s0lo);
    cudaGetSymbolAddress((void**)&cuh, g_curhi);
    cudaGetSymbolAddress((void**)&cul, g_curlo);
    cudaGetSymbolAddress((void**)&p0h, g_p0hi);
    cudaGetSymbolAddress((void**)&p0l, g_p0lo);
    cudaGetSymbolAddress((void**)&p1h, g_p1hi);
    cudaGetSymbolAddress((void**)&p1l, g_p1lo);

    prep_w_kernel<<<(3 * CDIM * KDIM + 255) / 256, 256>>>(W);
    pack_kernel<<<dim3(LMAX / 32, CDIM / 32, NB), dim3(32, 8)>>>(h, N, dout);

    // level 0 (merge): pairs from s0 -> cur (half prefix)
    mma_level_kernel<<<dim3(4, 32, NB), 256, SM_TOT>>>(
        s0h, s0l, s0h, s0l, cuh, cul, dout, bias, N, 0, LMAX, LMAX);
    // level 1: src cur (or s0 when half==0) -> p0
    mma_level_kernel<<<dim3(4, 32, NB), 256, SM_TOT>>>(
        cuh, cul, s0h, s0l, p0h, p0l, dout, bias, N, 1, LMAX, 2048);

    __nv_bfloat16* sh = p0h; __nv_bfloat16* sl = p0l;
    for (int lvl = 2; lvl <= 5; lvl++) {
        __nv_bfloat16* th = (lvl & 1) ? p0h : p1h;
        __nv_bfloat16* tl = (lvl & 1) ? p0l : p1l;
        int tiles = (LMAX >> lvl) / 64;
        mma_level_kernel<<<dim3(4, tiles, NB), 256, SM_TOT>>>(
            sh, sl, sh, sl, th, tl, dout, bias, N, lvl, 2048, 2048);
        sh = th; sl = tl;
    }
    for (int lvl = 6; lvl <= 12; lvl++) {
        __nv_bfloat16* th = (lvl & 1) ? p0h : p1h;
        __nv_bfloat16* tl = (lvl & 1) ? p0l : p1l;
        int pmax = LMAX >> lvl;
        gemm_small_kernel<<<dim3(8, (pmax + 7) / 8, NB), 192>>>(
            sh, sl, th, tl, dout, bias, N, lvl, 2048, 2048);
        sh = th; sl = tl;
    }
}